// round 11
// baseline (speedup 1.0000x reference)
#include <cuda_runtime.h>
#include <math.h>

#define BB 16
#define NN 131072
#define GG 16
#define BN (BB*NN)
#define NGB (BB*GG)          // 256 (b,g) pairs
#define NUNIT 2048           // scatter/loss work units (1024 pts each); 128 per batch
#define SPB  128             // slabs per batch
#define CCAP 2048            // candidate cap (expected ~300, huge margin)
#define GRID 1184            // 148 SMs x 8 resident CTAs — fully concurrent by construction

// ---------------- scratch (device globals; zero at load, re-zeroed by finalizer) ----------------
__device__ unsigned g_keys[BN];          // per-unit slabs of group-sorted keys (4KB each)
__device__ unsigned g_blkcnt[NUNIT * GG];// per-(unit,group) counts (overwritten every launch)
__device__ unsigned g_mg[BN / 4];        // packed (valid<<4)|group, one byte/point
__device__ float    g_inv[NGB];          // 1 / clamp(|median|, eps)
__device__ double   g_psum[32];          // distributed loss partials
__device__ unsigned g_tcnt[32];          // distributed valid-count partials
__device__ unsigned g_done;              // loss completion counter
__device__ unsigned g_arrive;            // grid-barrier arrive counter
__device__ volatile unsigned g_release;  // grid-barrier release generation

// order-preserving map f32 -> u32 (ascending)
__device__ __forceinline__ unsigned key_of(float z) {
    unsigned u = __float_as_uint(z);
    return (u & 0x80000000u) ? ~u : (u | 0x80000000u);
}

struct SmemScatter {
    unsigned cnt[32][16];
    unsigned gstart[17];
    uint4    keys4[256];
};
struct SmemSelect {
    unsigned off[SPB], c[SPB], dst[SPB];
    unsigned hist[2048];
    unsigned cand[CCAP];
};
union SmemU { SmemScatter sc; SmemSelect se; };

// all GRID blocks are resident (launch_bounds-enforced), so spinning is safe
__device__ __forceinline__ void grid_sync(unsigned gen) {
    __syncthreads();
    if (threadIdx.x == 0) {
        __threadfence();
        unsigned a = atomicAdd(&g_arrive, 1u) + 1u;
        if (a == gen * GRID) {
            g_release = gen;
        } else {
            while (g_release < gen) __nanosleep(64);
        }
        __threadfence();
    }
    __syncthreads();
}

__global__ void __launch_bounds__(256, 8)
k_fused(const float* __restrict__ pred, const float* __restrict__ target,
        const int* __restrict__ mask, const int* __restrict__ groups,
        float* __restrict__ out) {
    __shared__ SmemU sm;
    __shared__ unsigned s_wsum[8];
    __shared__ unsigned sh_sel, sh_k, sh_n, sh_app;
    __shared__ float sinv2[32];
    __shared__ float swarp[8];
    __shared__ int s_flag;
    int t = threadIdx.x, lane = t & 31, wid = t >> 5;

    // ================= Phase A: slab scatter (proven form), units strided =================
    for (unsigned u = blockIdx.x; u < NUNIT; u += GRID) {
        unsigned p0 = u * 1024u + t * 4u;
        ((unsigned*)sm.sc.cnt)[t] = 0;
        ((unsigned*)sm.sc.cnt)[256 + t] = 0;

        int4 m4 = *reinterpret_cast<const int4*>(mask + p0);
        int4 g4 = *reinterpret_cast<const int4*>(groups + p0);
        const float4* tt = reinterpret_cast<const float4*>(target + 3u * p0);
        float4 t0 = tt[0], t1 = tt[1], t2 = tt[2];
        int   m[4] = {m4.x, m4.y, m4.z, m4.w};
        int   g[4] = {g4.x & 15, g4.y & 15, g4.z & 15, g4.w & 15};
        float z[4] = {t0.z, t1.y, t2.x, t2.w};

        unsigned mg = 0;
#pragma unroll
        for (int e = 0; e < 4; e++)
            mg |= ((m[e] ? 0x10u : 0u) | (unsigned)g[e]) << (8 * e);
        g_mg[p0 >> 2] = mg;
        __syncthreads();

        unsigned peers[4];
#pragma unroll
        for (int e = 0; e < 4; e++) {
            unsigned tag = m[e] ? (unsigned)g[e] : 0xFFFFFFFFu;
            peers[e] = __match_any_sync(0xffffffffu, tag);
            if (m[e] && lane == (__ffs(peers[e]) - 1))
                sm.sc.cnt[wid * 4 + e][g[e]] = __popc(peers[e]);
        }
        __syncthreads();

        if (t < 16) {
            unsigned run = 0;
#pragma unroll
            for (int s = 0; s < 32; s++) {
                unsigned c = sm.sc.cnt[s][t];
                sm.sc.cnt[s][t] = run;
                run += c;
            }
            unsigned incl = run;
#pragma unroll
            for (int o = 1; o < 16; o <<= 1) {
                unsigned n = __shfl_up_sync(0x0000FFFFu, incl, o);
                if (lane >= o) incl += n;
            }
            sm.sc.gstart[t] = incl - run;
            if (t == 15) sm.sc.gstart[16] = incl;
            g_blkcnt[u * GG + t] = run;
        }
        __syncthreads();

#pragma unroll
        for (int e = 0; e < 4; e++) {
            if (m[e]) {
                unsigned local = sm.sc.gstart[g[e]] + sm.sc.cnt[wid * 4 + e][g[e]]
                               + __popc(peers[e] & ((1u << lane) - 1u));
                ((unsigned*)sm.sc.keys4)[local] = key_of(z[e]);
            }
        }
        __syncthreads();

        unsigned nvec = (sm.sc.gstart[16] + 3u) >> 2;
        uint4* dst = reinterpret_cast<uint4*>(g_keys + u * 1024u);
        for (unsigned i = t; i < nvec; i += 256u) dst[i] = sm.sc.keys4[i];
        __syncthreads();
    }

    grid_sync(1);

    // ================= Phase B: select (blocks 0..255), slabs re-streamed from L2 =========
    if (blockIdx.x < NGB) {
        int bg = blockIdx.x;
        int b = bg >> 4, g = bg & 15;

        // per-slab run offset/count + destination prefix
        unsigned my_incl = 0, my_c = 0;
        if (t < SPB) {
            const uint4* p = reinterpret_cast<const uint4*>(g_blkcnt + (unsigned)(b * SPB + t) * GG);
            uint4 c0 = p[0], c1 = p[1], c2 = p[2], c3 = p[3];
            unsigned cc[16] = {c0.x, c0.y, c0.z, c0.w, c1.x, c1.y, c1.z, c1.w,
                               c2.x, c2.y, c2.z, c2.w, c3.x, c3.y, c3.z, c3.w};
            unsigned start = 0;
            for (int j = 0; j < g; j++) start += cc[j];
            my_c = cc[g];
            sm.se.off[t] = start;
            sm.se.c[t] = my_c;
            my_incl = my_c;
#pragma unroll
            for (int o = 1; o < 32; o <<= 1) {
                unsigned n = __shfl_up_sync(0xffffffffu, my_incl, o);
                if (lane >= o) my_incl += n;
            }
            if (lane == 31) s_wsum[wid] = my_incl;
        }
        for (int i = t; i < 2048; i += 256) sm.se.hist[i] = 0;
        __syncthreads();
        if (t < SPB) {
            unsigned off = 0;
#pragma unroll
            for (int w = 0; w < 4; w++) off += (w < wid) ? s_wsum[w] : 0u;
            sm.se.dst[t] = off + my_incl - my_c;
        }
        __syncthreads();
        unsigned cnt = sm.se.dst[SPB - 1] + sm.se.c[SPB - 1];
        if (t == 0 && cnt) atomicAdd(&g_tcnt[bg & 31], cnt);
        if (cnt == 0) {
            if (t == 0) g_inv[bg] = 1.0f;
        } else {
            // level-1 histogram (bins = key >> 21) streaming slab runs (L2-hot)
            for (int s = wid; s < SPB; s += 8) {
                unsigned c = sm.se.c[s];
                const unsigned* src = g_keys + (unsigned)(b * SPB + s) * 1024u + sm.se.off[s];
                for (unsigned j = lane; j < c; j += 32u)
                    atomicAdd(&sm.se.hist[src[j] >> 21], 1u);
            }
            __syncthreads();

            auto scan_pick = [&](int nbins, unsigned kk) {
                int per = nbins >> 8;             // 8 or 4 bins per thread (256 threads)
                unsigned hh[8];
                unsigned sum = 0;
                for (int j = 0; j < per; j++) { hh[j] = sm.se.hist[t * per + j]; sum += hh[j]; }
                unsigned incl = sum;
#pragma unroll
                for (int o = 1; o < 32; o <<= 1) {
                    unsigned n = __shfl_up_sync(0xffffffffu, incl, o);
                    if (lane >= o) incl += n;
                }
                if (lane == 31) s_wsum[wid] = incl;
                __syncthreads();
                unsigned off = 0;
#pragma unroll
                for (int w = 0; w < 8; w++) off += (w < wid) ? s_wsum[w] : 0u;
                incl += off;
                unsigned excl = incl - sum;
                if (kk >= excl && kk < incl) {
                    unsigned r = kk - excl;
                    for (int j = 0; j < per; j++) {
                        if (r < hh[j]) { sh_sel = (unsigned)(t * per + j); sh_k = r; sh_n = hh[j]; break; }
                        r -= hh[j];
                    }
                }
                __syncthreads();
            };

            unsigned k = (cnt - 1u) >> 1;
            scan_pick(2048, k);
            unsigned sel0 = sh_sel; k = sh_k;
            unsigned ncand = sh_n;
            bool fits2 = (ncand <= CCAP);

            // collect candidates with top-11 == sel0 (re-stream runs, ballot append)
            if (t == 0) sh_app = 0;
            __syncthreads();
            if (fits2) {
                for (int s = wid; s < SPB; s += 8) {
                    unsigned c = sm.se.c[s];
                    const unsigned* src = g_keys + (unsigned)(b * SPB + s) * 1024u + sm.se.off[s];
                    unsigned lim = (c + 31u) & ~31u;
                    for (unsigned j = lane; j < lim; j += 32u) {
                        bool ok = (j < c) && ((src[j] >> 21) == sel0);
                        unsigned key = ok ? src[j] : 0u;
                        unsigned bal = __ballot_sync(0xffffffffu, ok);
                        unsigned base = 0;
                        if (lane == 0 && bal) base = atomicAdd(&sh_app, (unsigned)__popc(bal));
                        base = __shfl_sync(0xffffffffu, base, 0);
                        if (ok) sm.se.cand[base + __popc(bal & ((1u << lane) - 1u))] = key;
                    }
                }
            }
            __syncthreads();

            // level 2: bins = (key >> 10) & 2047
            for (int i = t; i < 2048; i += 256) sm.se.hist[i] = 0;
            __syncthreads();
            if (fits2) {
                for (unsigned i = t; i < ncand; i += 256u)
                    atomicAdd(&sm.se.hist[(sm.se.cand[i] >> 10) & 2047u], 1u);
            } else {
                for (int s = wid; s < SPB; s += 8) {
                    unsigned c = sm.se.c[s];
                    const unsigned* src = g_keys + (unsigned)(b * SPB + s) * 1024u + sm.se.off[s];
                    for (unsigned j = lane; j < c; j += 32u) {
                        unsigned key = src[j];
                        if ((key >> 21) == sel0) atomicAdd(&sm.se.hist[(key >> 10) & 2047u], 1u);
                    }
                }
            }
            __syncthreads();
            scan_pick(2048, k);
            unsigned sel1 = sh_sel; k = sh_k;
            unsigned pfx22 = (sel0 << 11) | sel1;

            // level 3: bins = key & 1023
            for (int i = t; i < 1024; i += 256) sm.se.hist[i] = 0;
            __syncthreads();
            if (fits2) {
                for (unsigned i = t; i < ncand; i += 256u) {
                    unsigned key = sm.se.cand[i];
                    if ((key >> 10) == pfx22) atomicAdd(&sm.se.hist[key & 1023u], 1u);
                }
            } else {
                for (int s = wid; s < SPB; s += 8) {
                    unsigned c = sm.se.c[s];
                    const unsigned* src = g_keys + (unsigned)(b * SPB + s) * 1024u + sm.se.off[s];
                    for (unsigned j = lane; j < c; j += 32u) {
                        unsigned key = src[j];
                        if ((key >> 10) == pfx22) atomicAdd(&sm.se.hist[key & 1023u], 1u);
                    }
                }
            }
            __syncthreads();
            scan_pick(1024, k);

            if (t == 0) {
                unsigned kk = (pfx22 << 10) | sh_sel;
                unsigned ub = (kk & 0x80000000u) ? (kk & 0x7fffffffu) : ~kk;
                float med = __uint_as_float(ub);
                if (!isfinite(med)) med = 1.0f;
                float ns = fmaxf(fabsf(med), 1e-6f);
                g_inv[bg] = 1.0f / ns;
            }
        }
    }

    grid_sync(2);

    // ================= Phase C: branchless loss (proven 4pt form), units strided ==========
    float acc = 0.f;
    for (unsigned u = blockIdx.x; u < NUNIT; u += GRID) {
        int b = u >> 7;
        if (t < 32)
            sinv2[t] = (t >= 16) ? g_inv[b * GG + (t & 15)] : 0.f;
        __syncthreads();
        unsigned p0 = u * 1024u + t * 4u;
        unsigned mg = __ldg(&g_mg[p0 >> 2]);
        const float4* pp = reinterpret_cast<const float4*>(pred + 3u * p0);
        const float4* tt = reinterpret_cast<const float4*>(target + 3u * p0);
        float4 pa = pp[0], pb = pp[1], pc = pp[2];
        float4 ta = tt[0], tb = tt[1], tc = tt[2];
        float pr[12] = {pa.x, pa.y, pa.z, pa.w, pb.x, pb.y, pb.z, pb.w, pc.x, pc.y, pc.z, pc.w};
        float tr[12] = {ta.x, ta.y, ta.z, ta.w, tb.x, tb.y, tb.z, tb.w, tc.x, tc.y, tc.z, tc.w};
#pragma unroll
        for (int e = 0; e < 4; e++) {
            float inv = sinv2[(mg >> (8 * e)) & 0xFFu];
#pragma unroll
            for (int c = 0; c < 3; c++) {
                float p = pr[e * 3 + c] * inv;
                float tv = tr[e * 3 + c] * inv;
                float uu = fabsf(p); if (!(uu <= 3.0e38f)) uu = 0.f;
                float vv = fabsf(tv); if (!(vv <= 3.0e38f)) vv = 0.f;
                float a = 1.f + uu, q = 1.f + vv;
                bool same = (__float_as_uint(p) >> 31) == (__float_as_uint(tv) >> 31);
                float r = same ? __fdividef(a, q) : a * q;
                acc += fabsf(__logf(r));
            }
        }
        __syncthreads();
    }
#pragma unroll
    for (int o = 16; o; o >>= 1) acc += __shfl_down_sync(0xffffffffu, acc, o);
    if (lane == 0) swarp[wid] = acc;
    __syncthreads();
    if (t == 0) {
        float s = 0.f;
#pragma unroll
        for (int w = 0; w < 8; w++) s += swarp[w];
        atomicAdd(&g_psum[blockIdx.x & 31], (double)s);
        __threadfence();
        unsigned d = atomicAdd(&g_done, 1u);
        s_flag = (d == GRID - 1u);
    }
    __syncthreads();
    if (s_flag && t == 0) {
        unsigned total = 0;
#pragma unroll
        for (int j = 0; j < 32; j++) total += g_tcnt[j];
        double ssum = 0.0;
#pragma unroll
        for (int j = 0; j < 32; j++) ssum += g_psum[j];
        out[0] = (float)(ssum / (3.0 * (double)total + 1e-6));
        // restore ALL scratch state for the next (graph-replayed) launch
#pragma unroll
        for (int j = 0; j < 32; j++) { g_psum[j] = 0.0; g_tcnt[j] = 0u; }
        g_done = 0u;
        g_arrive = 0u;
        g_release = 0u;
    }
}

extern "C" void kernel_launch(void* const* d_in, const int* in_sizes, int n_in,
                              void* d_out, int out_size) {
    const float* pred   = (const float*)d_in[0];
    const float* target = (const float*)d_in[1];
    const int*   mask   = (const int*)d_in[2];
    const int*   groups = (const int*)d_in[3];
    float* out = (float*)d_out;
    (void)in_sizes; (void)n_in; (void)out_size;

    k_fused<<<GRID, 256>>>(pred, target, mask, groups, out);
}